// round 12
// baseline (speedup 1.0000x reference)
#include <cuda_runtime.h>
#include <math_constants.h>

// ROI max pooling: feature_map [B=2, H=38, W=38, C=512] f32, rois [B,N=64,4] i32 (y,x,h,w)
// output [B, N, 7, 7, C] f32.
//
// One block per (roi, cell): grid = B*N*49 = 6272 blocks, 128 threads, one
// float4/thread over C=512. R7 profile showed nothing saturated (L2 35%,
// L1 30%, issue 44%) -> latency/MLP-bound. This version unrolls 2x2 over
// (y,x) with clamped indices (duplicates are no-ops for max, and hit L1),
// giving 4 independent LDG.128 in flight per thread instead of ~2.

#define B_ 2
#define N_ 64
#define H_ 38
#define W_ 38
#define C4_ 128   // C/4 = 512/4
#define P_ 7
#define PP_ 49

#define FMAX4(dst, v) do {                       \
    (dst).x = fmaxf((dst).x, (v).x);             \
    (dst).y = fmaxf((dst).y, (v).y);             \
    (dst).z = fmaxf((dst).z, (v).z);             \
    (dst).w = fmaxf((dst).w, (v).w); } while (0)

__global__ __launch_bounds__(128, 8)
void roi_pool_kernel(const float4* __restrict__ fm,
                     const int4* __restrict__ rois,
                     float4* __restrict__ out) {
    const int cell = blockIdx.x % PP_;
    const int roi  = blockIdx.x / PP_;          // roi = b*N + n
    const int b    = roi >> 6;                  // N = 64

    const int4 r = __ldg(&rois[roi]);           // (y0, x0, h, w)
    const int y0 = r.x, x0 = r.y, h = r.z, w = r.w;

    const int py = cell / P_;
    const int px = cell % P_;

    // bin [floor(py*h/P), floor((py+1)*h/P)) — identical to ref's (P*r + P-1)//h assignment
    const int ys = y0 + (py * h) / P_;
    const int ye = y0 + ((py + 1) * h) / P_;
    const int xs = x0 + (px * w) / P_;
    const int xe = x0 + ((px + 1) * w) / P_;

    const int c = threadIdx.x;                  // 0..127 (float4 channel index)

    const float4 ninf = make_float4(-CUDART_INF_F, -CUDART_INF_F,
                                    -CUDART_INF_F, -CUDART_INF_F);
    float4 m00 = ninf, m01 = ninf, m10 = ninf, m11 = ninf;

    #pragma unroll 1
    for (int y = ys; y < ye; y += 2) {
        const int y1 = (y + 1 < ye) ? (y + 1) : y;     // clamp: duplicate row ok for max
        const float4* p0 = fm + ((size_t)(b * H_ + y)  * W_) * C4_ + c;
        const float4* p1 = fm + ((size_t)(b * H_ + y1) * W_) * C4_ + c;
        #pragma unroll 1
        for (int x = xs; x < xe; x += 2) {
            const int x1 = (x + 1 < xe) ? (x + 1) : x; // clamp: duplicate col ok for max
            // 4 independent LDG.128, 4 independent accumulators
            float4 v00 = __ldg(p0 + (size_t)x  * C4_);
            float4 v01 = __ldg(p0 + (size_t)x1 * C4_);
            float4 v10 = __ldg(p1 + (size_t)x  * C4_);
            float4 v11 = __ldg(p1 + (size_t)x1 * C4_);
            FMAX4(m00, v00);
            FMAX4(m01, v01);
            FMAX4(m10, v10);
            FMAX4(m11, v11);
        }
    }

    FMAX4(m00, m01);
    FMAX4(m10, m11);
    FMAX4(m00, m10);

    // out layout [B,N,7,7,C]: linear cell index == blockIdx.x
    out[(size_t)blockIdx.x * C4_ + c] = m00;
}

extern "C" void kernel_launch(void* const* d_in, const int* in_sizes, int n_in,
                              void* d_out, int out_size) {
    const float4* fm  = (const float4*)d_in[0];
    const int4* rois  = (const int4*)d_in[1];
    float4* out       = (float4*)d_out;

    dim3 grid(B_ * N_ * PP_);
    dim3 block(128);
    roi_pool_kernel<<<grid, block>>>(fm, rois, out);
}